// round 2
// baseline (speedup 1.0000x reference)
#include <cuda_runtime.h>

// Problem constants
#define B_  8
#define H_  256
#define W_  256
#define P_  8
#define PH_ 32
#define N_  1024   // PH*PH
#define S_  64     // P*P
#define T_  64
#define INV_TEMP 10.0f
#define LN_EPS 1e-5f

__global__ __launch_bounds__(256, 8)
void scs_kernel(const float* __restrict__ spikes,
                const float* __restrict__ Wd,
                const float* __restrict__ gamma,
                const float* __restrict__ beta,
                const float* __restrict__ gates,
                const float* __restrict__ biases,
                float* __restrict__ out) {
    __shared__ float s_patch[64];
    __shared__ float s_out[64];
    __shared__ float s_final[64];

    const int blk = blockIdx.x;      // b*1024 + n
    const int b   = blk >> 10;
    const int n   = blk & 1023;
    const int py  = n >> 5;
    const int px  = n & 31;
    const int tid = threadIdx.x;

    // ---- load 8x8 patch into shared (unfold) ----
    const float* sp = spikes + ((size_t)b << 16) + ((py << 3) * 256) + (px << 3);
    if (tid < 64) {
        const int r = tid >> 3, c = tid & 7;
        s_patch[tid] = sp[r * 256 + c];
    }

    // ---- issue the 4 streaming W loads EARLY (before the sync): MLP=4/thread ----
    // thread tid = t*4 + j handles floats [tid*16, tid*16+16) of the 4096-float tile
    const float4* Wp = (const float4*)(Wd + ((size_t)blk << 12));
    float4 w0 = __ldcs(&Wp[(tid << 2) + 0]);
    float4 w1 = __ldcs(&Wp[(tid << 2) + 1]);
    float4 w2 = __ldcs(&Wp[(tid << 2) + 2]);
    float4 w3 = __ldcs(&Wp[(tid << 2) + 3]);

    __syncthreads();

    const int t = tid >> 2;
    const int j = tid & 3;
    const float4* pp = (const float4*)s_patch;
    const float4 p0 = pp[(j << 2) + 0];
    const float4 p1 = pp[(j << 2) + 1];
    const float4 p2 = pp[(j << 2) + 2];
    const float4 p3 = pp[(j << 2) + 3];

    float acc = w0.x * p0.x + w0.y * p0.y + w0.z * p0.z + w0.w * p0.w;
    acc      += w1.x * p1.x + w1.y * p1.y + w1.z * p1.z + w1.w * p1.w;
    acc      += w2.x * p2.x + w2.y * p2.y + w2.z * p2.z + w2.w * p2.w;
    acc      += w3.x * p3.x + w3.y * p3.y + w3.z * p3.z + w3.w * p3.w;

    // reduce across the 4-thread group (same warp)
    acc += __shfl_xor_sync(0xffffffffu, acc, 1);
    acc += __shfl_xor_sync(0xffffffffu, acc, 2);
    if (j == 0) s_out[t] = acc;
    __syncthreads();

    // ---- warp 0: LayerNorm + softmax(/0.1) + gated affine over T=64 ----
    if (tid < 32) {
        const float v0 = s_out[tid];
        const float v1 = s_out[tid + 32];
        const float q0 = s_patch[tid];
        const float q1 = s_patch[tid + 32];

        float ps = q0 + q1;          // patch sum
        float sm = v0 + v1;          // out sum
#pragma unroll
        for (int o = 16; o > 0; o >>= 1) {
            ps += __shfl_xor_sync(0xffffffffu, ps, o);
            sm += __shfl_xor_sync(0xffffffffu, sm, o);
        }
        const float mu = sm * (1.0f / 64.0f);
        const float d0 = v0 - mu, d1 = v1 - mu;
        float sq = d0 * d0 + d1 * d1;
#pragma unroll
        for (int o = 16; o > 0; o >>= 1)
            sq += __shfl_xor_sync(0xffffffffu, sq, o);
        const float rstd = rsqrtf(sq * (1.0f / 64.0f) + LN_EPS);

        const float z0 = (d0 * rstd * __ldg(&gamma[tid])      + __ldg(&beta[tid]))      * INV_TEMP;
        const float z1 = (d1 * rstd * __ldg(&gamma[tid + 32]) + __ldg(&beta[tid + 32])) * INV_TEMP;

        float mx = fmaxf(z0, z1);
#pragma unroll
        for (int o = 16; o > 0; o >>= 1)
            mx = fmaxf(mx, __shfl_xor_sync(0xffffffffu, mx, o));

        const float e0 = __expf(z0 - mx);
        const float e1 = __expf(z1 - mx);
        float se = e0 + e1;
#pragma unroll
        for (int o = 16; o > 0; o >>= 1)
            se += __shfl_xor_sync(0xffffffffu, se, o);

        const float affine = __ldg(&gates[n]) * ps + __ldg(&biases[n]);
        const float scale  = affine / se;
        s_final[tid]      = e0 * scale;
        s_final[tid + 32] = e1 * scale;
    }
    __syncthreads();

    // ---- fold back to [B, H, W] ----
    if (tid < 64) {
        const int r = tid >> 3, c = tid & 7;
        out[((size_t)b << 16) + ((py << 3) + r) * 256 + (px << 3) + c] = s_final[tid];
    }
}

extern "C" void kernel_launch(void* const* d_in, const int* in_sizes, int n_in,
                              void* d_out, int out_size) {
    const float* spikes = (const float*)d_in[0];
    const float* Wd     = (const float*)d_in[1];
    const float* gamma  = (const float*)d_in[2];
    const float* beta   = (const float*)d_in[3];
    const float* gates  = (const float*)d_in[4];
    const float* biases = (const float*)d_in[5];
    float* out = (float*)d_out;

    scs_kernel<<<B_ * N_, 256>>>(spikes, Wd, gamma, beta, gates, biases, out);
}

// round 3
// speedup vs baseline: 1.4528x; 1.4528x over previous
#include <cuda_runtime.h>

// Problem constants
#define B_  8
#define H_  256
#define W_  256
#define P_  8
#define PH_ 32
#define N_  1024   // PH*PH
#define S_  64     // P*P
#define T_  64
#define INV_TEMP 10.0f
#define LN_EPS 1e-5f

__global__ __launch_bounds__(256, 8)
void scs_kernel(const float* __restrict__ spikes,
                const float* __restrict__ Wd,
                const float* __restrict__ gamma,
                const float* __restrict__ beta,
                const float* __restrict__ gates,
                const float* __restrict__ biases,
                float* __restrict__ out) {
    __shared__ float s_patch[64];
    __shared__ float s_out[64];
    __shared__ float s_final[64];

    const int blk = blockIdx.x;      // b*1024 + n
    const int b   = blk >> 10;
    const int n   = blk & 1023;
    const int py  = n >> 5;
    const int px  = n & 31;
    const int tid = threadIdx.x;

    // ---- load 8x8 patch into shared (unfold) ----
    const float* sp = spikes + ((size_t)b << 16) + ((py << 3) * 256) + (px << 3);
    if (tid < 64) {
        const int r = tid >> 3, c = tid & 7;
        s_patch[tid] = sp[r * 256 + c];
    }

    // ---- streaming W loads, WARP-CONTIGUOUS (512B per warp instruction) ----
    // Tile = 1024 float4. Thread tid loads float4 indices {tid, tid+256, tid+512, tid+768}.
    // float4 index f belongs to row f>>4, row-part j' = f&15.
    // For fixed tid: j' = tid&15 for all four loads; row_k = (tid>>4) + 16*k.
    const float4* Wp = (const float4*)(Wd + ((size_t)blk << 12));
    float4 w0 = __ldcs(Wp + tid);
    float4 w1 = __ldcs(Wp + tid + 256);
    float4 w2 = __ldcs(Wp + tid + 512);
    float4 w3 = __ldcs(Wp + tid + 768);

    __syncthreads();

    const int jp = tid & 15;
    const float4 p = ((const float4*)s_patch)[jp];   // broadcast within 16-lane group

    float a0 = w0.x * p.x + w0.y * p.y + w0.z * p.z + w0.w * p.w;
    float a1 = w1.x * p.x + w1.y * p.y + w1.z * p.z + w1.w * p.w;
    float a2 = w2.x * p.x + w2.y * p.y + w2.z * p.z + w2.w * p.w;
    float a3 = w3.x * p.x + w3.y * p.y + w3.z * p.z + w3.w * p.w;

    // reduce each accumulator across its 16-lane group (lanes sharing tid>>4)
#pragma unroll
    for (int o = 1; o < 16; o <<= 1) {
        a0 += __shfl_xor_sync(0xffffffffu, a0, o);
        a1 += __shfl_xor_sync(0xffffffffu, a1, o);
        a2 += __shfl_xor_sync(0xffffffffu, a2, o);
        a3 += __shfl_xor_sync(0xffffffffu, a3, o);
    }
    if (jp == 0) {
        const int r0 = tid >> 4;          // 0..15
        s_out[r0]      = a0;
        s_out[r0 + 16] = a1;
        s_out[r0 + 32] = a2;
        s_out[r0 + 48] = a3;
    }
    __syncthreads();

    // ---- warp 0: LayerNorm + softmax(/0.1) + gated affine over T=64 ----
    if (tid < 32) {
        const float v0 = s_out[tid];
        const float v1 = s_out[tid + 32];
        const float q0 = s_patch[tid];
        const float q1 = s_patch[tid + 32];

        float ps = q0 + q1;          // patch sum
        float sm = v0 + v1;          // out sum
#pragma unroll
        for (int o = 16; o > 0; o >>= 1) {
            ps += __shfl_xor_sync(0xffffffffu, ps, o);
            sm += __shfl_xor_sync(0xffffffffu, sm, o);
        }
        const float mu = sm * (1.0f / 64.0f);
        const float d0 = v0 - mu, d1 = v1 - mu;
        float sq = d0 * d0 + d1 * d1;
#pragma unroll
        for (int o = 16; o > 0; o >>= 1)
            sq += __shfl_xor_sync(0xffffffffu, sq, o);
        const float rstd = rsqrtf(sq * (1.0f / 64.0f) + LN_EPS);

        const float z0 = (d0 * rstd * __ldg(&gamma[tid])      + __ldg(&beta[tid]))      * INV_TEMP;
        const float z1 = (d1 * rstd * __ldg(&gamma[tid + 32]) + __ldg(&beta[tid + 32])) * INV_TEMP;

        float mx = fmaxf(z0, z1);
#pragma unroll
        for (int o = 16; o > 0; o >>= 1)
            mx = fmaxf(mx, __shfl_xor_sync(0xffffffffu, mx, o));

        const float e0 = __expf(z0 - mx);
        const float e1 = __expf(z1 - mx);
        float se = e0 + e1;
#pragma unroll
        for (int o = 16; o > 0; o >>= 1)
            se += __shfl_xor_sync(0xffffffffu, se, o);

        const float affine = __ldg(&gates[n]) * ps + __ldg(&biases[n]);
        const float scale  = affine / se;
        s_final[tid]      = e0 * scale;
        s_final[tid + 32] = e1 * scale;
    }
    __syncthreads();

    // ---- fold back to [B, H, W] ----
    if (tid < 64) {
        const int r = tid >> 3, c = tid & 7;
        out[((size_t)b << 16) + ((py << 3) + r) * 256 + (px << 3) + c] = s_final[tid];
    }
}

extern "C" void kernel_launch(void* const* d_in, const int* in_sizes, int n_in,
                              void* d_out, int out_size) {
    const float* spikes = (const float*)d_in[0];
    const float* Wd     = (const float*)d_in[1];
    const float* gamma  = (const float*)d_in[2];
    const float* beta   = (const float*)d_in[3];
    const float* gates  = (const float*)d_in[4];
    const float* biases = (const float*)d_in[5];
    float* out = (float*)d_out;

    scs_kernel<<<B_ * N_, 256>>>(spikes, Wd, gamma, beta, gates, biases, out);
}